// round 1
// baseline (speedup 1.0000x reference)
#include <cuda_runtime.h>

#define HID 64

__global__ void zero_kernel(float* __restrict__ out, int n) {
    int i = blockIdx.x * blockDim.x + threadIdx.x;
    if (i < n) out[i] = 0.0f;
}

// One kernel per edge family. DIN = 3 (2-body / self) or 6 (3-body).
// EPT = edges per thread (register blocking so smem weight loads amortize).
template<int DIN, int EPT>
__global__ __launch_bounds__(128)
void edge_mlp_scatter_kernel(
    const float* __restrict__ x,       // [N,3]
    const int*   __restrict__ edges,   // [DIN==3 ? 2 : 3, E] row-major
    const float* __restrict__ attr,    // [E,3]
    const float* __restrict__ W1,      // [DIN,HID]
    const float* __restrict__ b1,      // [HID]
    const float* __restrict__ W2,      // [HID,9]
    const float* __restrict__ b2,      // [9]
    float*       __restrict__ out,     // [N,3]
    int E)
{
    __shared__ float sW1[DIN * HID];
    __shared__ float sB1[HID];
    __shared__ float sW2[HID * 9];
    __shared__ float sB2[9];

    for (int i = threadIdx.x; i < DIN * HID; i += blockDim.x) sW1[i] = W1[i];
    for (int i = threadIdx.x; i < HID;       i += blockDim.x) sB1[i] = b1[i];
    for (int i = threadIdx.x; i < HID * 9;   i += blockDim.x) sW2[i] = W2[i];
    if (threadIdx.x < 9) sB2[threadIdx.x] = b2[threadIdx.x];
    __syncthreads();

    const int tid    = blockIdx.x * blockDim.x + threadIdx.x;
    const int stride = gridDim.x * blockDim.x;

    float d[EPT][DIN];      // MLP input per edge
    float at[EPT][3];       // edge attr
    float acc[EPT][9];      // mobility accumulator (init b2)
    int   tgt[EPT];
    bool  valid[EPT];

    #pragma unroll
    for (int k = 0; k < EPT; k++) {
        int e = tid + k * stride;
        valid[k] = (e < E);
        int ee = valid[k] ? e : 0;
        if (DIN == 3) {
            int j = edges[ee];          // source
            int i = edges[E + ee];      // target
            tgt[k] = i;
            float xj0 = x[3*j], xj1 = x[3*j+1], xj2 = x[3*j+2];
            float xi0 = x[3*i], xi1 = x[3*i+1], xi2 = x[3*i+2];
            d[k][0] = xj0 - xi0;
            d[k][1] = xj1 - xi1;
            d[k][2] = xj2 - xi2;
        } else {
            int j  = edges[ee];         // row0: j
            int kk = edges[E + ee];     // row1: k
            int i  = edges[2*E + ee];   // row2: i (target)
            tgt[k] = i;
            float xj0 = x[3*j],  xj1 = x[3*j+1],  xj2 = x[3*j+2];
            float xk0 = x[3*kk], xk1 = x[3*kk+1], xk2 = x[3*kk+2];
            float xi0 = x[3*i],  xi1 = x[3*i+1],  xi2 = x[3*i+2];
            d[k][0] = xk0 - xj0;
            d[k][1] = xk1 - xj1;
            d[k][2] = xk2 - xj2;
            d[k][3] = xi0 - xk0;
            d[k][4] = xi1 - xk1;
            d[k][5] = xi2 - xk2;
        }
        at[k][0] = attr[3*ee + 0];
        at[k][1] = attr[3*ee + 1];
        at[k][2] = attr[3*ee + 2];
        #pragma unroll
        for (int m = 0; m < 9; m++) acc[k][m] = sB2[m];
    }

    // Mainloop over hidden units: per h, load weights once from smem,
    // apply to EPT edges.
    #pragma unroll 4
    for (int h = 0; h < HID; h++) {
        float w1c[DIN];
        #pragma unroll
        for (int i = 0; i < DIN; i++) w1c[i] = sW1[i * HID + h];
        float bh = sB1[h];
        float w2r[9];
        #pragma unroll
        for (int m = 0; m < 9; m++) w2r[m] = sW2[h * 9 + m];

        #pragma unroll
        for (int k = 0; k < EPT; k++) {
            float hv = bh;
            #pragma unroll
            for (int i = 0; i < DIN; i++) hv = fmaf(d[k][i], w1c[i], hv);
            hv = fmaxf(hv, 0.0f);
            #pragma unroll
            for (int m = 0; m < 9; m++) acc[k][m] = fmaf(hv, w2r[m], acc[k][m]);
        }
    }

    // Epilogue: y_i = mob[i][:] . attr ; scatter-add to target node.
    #pragma unroll
    for (int k = 0; k < EPT; k++) {
        if (!valid[k]) continue;
        #pragma unroll
        for (int i = 0; i < 3; i++) {
            float y = fmaf(acc[k][3*i + 0], at[k][0],
                      fmaf(acc[k][3*i + 1], at[k][1],
                           acc[k][3*i + 2] * at[k][2]));
            atomicAdd(&out[3 * tgt[k] + i], y);
        }
    }
}

extern "C" void kernel_launch(void* const* d_in, const int* in_sizes, int n_in,
                              void* d_out, int out_size)
{
    const float* x   = (const float*)d_in[0];
    const int*   e2  = (const int*)  d_in[1];
    const int*   e3  = (const int*)  d_in[2];
    const int*   es  = (const int*)  d_in[3];
    // d_in[4] = edge_1body (unused)
    const float* a2  = (const float*)d_in[5];
    const float* a3  = (const float*)d_in[6];
    const float* as  = (const float*)d_in[7];
    // d_in[8] = edge_attr_1body (unused)
    const float* W1_2b = (const float*)d_in[9];
    const float* b1_2b = (const float*)d_in[10];
    const float* W2_2b = (const float*)d_in[11];
    const float* b2_2b = (const float*)d_in[12];
    const float* W1_3b = (const float*)d_in[13];
    const float* b1_3b = (const float*)d_in[14];
    const float* W2_3b = (const float*)d_in[15];
    const float* b2_3b = (const float*)d_in[16];
    const float* W1_s  = (const float*)d_in[17];
    const float* b1_s  = (const float*)d_in[18];
    const float* W2_s  = (const float*)d_in[19];
    const float* b2_s  = (const float*)d_in[20];

    const int E2 = in_sizes[1] / 2;
    const int E3 = in_sizes[2] / 3;
    const int ES = in_sizes[3] / 2;

    float* out = (float*)d_out;

    // Zero the output (it is poisoned before each timed run).
    zero_kernel<<<(out_size + 255) / 256, 256>>>(out, out_size);

    constexpr int EPT = 4;
    constexpr int BLK = 128;

    {
        int threads = (E2 + EPT - 1) / EPT;
        int blocks  = (threads + BLK - 1) / BLK;
        edge_mlp_scatter_kernel<3, EPT><<<blocks, BLK>>>(
            x, e2, a2, W1_2b, b1_2b, W2_2b, b2_2b, out, E2);
    }
    {
        int threads = (E3 + EPT - 1) / EPT;
        int blocks  = (threads + BLK - 1) / BLK;
        edge_mlp_scatter_kernel<6, EPT><<<blocks, BLK>>>(
            x, e3, a3, W1_3b, b1_3b, W2_3b, b2_3b, out, E3);
    }
    {
        int threads = (ES + EPT - 1) / EPT;
        int blocks  = (threads + BLK - 1) / BLK;
        edge_mlp_scatter_kernel<3, EPT><<<blocks, BLK>>>(
            x, es, as, W1_s, b1_s, W2_s, b2_s, out, ES);
    }
}

// round 2
// speedup vs baseline: 1.1477x; 1.1477x over previous
#include <cuda_runtime.h>

#define HID 64
typedef unsigned long long u64;

__device__ __forceinline__ u64 pk2(float lo, float hi) {
    u64 r; asm("mov.b64 %0, {%1,%2};" : "=l"(r) : "f"(lo), "f"(hi)); return r;
}
__device__ __forceinline__ void upk2(u64 v, float& lo, float& hi) {
    asm("mov.b64 {%0,%1}, %2;" : "=f"(lo), "=f"(hi) : "l"(v));
}
__device__ __forceinline__ u64 ffma2(u64 a, u64 b, u64 c) {
    u64 d; asm("fma.rn.f32x2 %0, %1, %2, %3;" : "=l"(d) : "l"(a), "l"(b), "l"(c)); return d;
}
__device__ __forceinline__ u64 fmul2(u64 a, u64 b) {
    u64 d; asm("mul.rn.f32x2 %0, %1, %2;" : "=l"(d) : "l"(a), "l"(b)); return d;
}

__global__ void zero_kernel(float* __restrict__ out, int n) {
    int i = blockIdx.x * blockDim.x + threadIdx.x;
    if (i < n) out[i] = 0.0f;
}

// Process one edge family. DIN = 3 or 6. EPT edges per thread, packed in pairs.
// Weights live in smem PRE-DUPLICATED as (w,w) 64-bit pairs so LDS.64 feeds
// fma.rn.f32x2 directly.
template<int DIN, int EPT>
__device__ __forceinline__ void run_family(
    const float* __restrict__ x,
    const int*   __restrict__ edges,
    const float* __restrict__ attr,
    const float* __restrict__ W1, const float* __restrict__ b1,
    const float* __restrict__ W2, const float* __restrict__ b2,
    float* __restrict__ out, int E, int blk, int nblk, u64* smem)
{
    u64* sW1 = smem;                 // [DIN*HID] dup pairs
    u64* sB1 = sW1 + (size_t)DIN * HID;  // [HID]
    u64* sW2 = sB1 + HID;            // [HID*9]
    u64* sB2 = sW2 + HID * 9;        // [9]

    for (int i = threadIdx.x; i < DIN * HID; i += blockDim.x) { float w = W1[i]; sW1[i] = pk2(w, w); }
    for (int i = threadIdx.x; i < HID;       i += blockDim.x) { float w = b1[i]; sB1[i] = pk2(w, w); }
    for (int i = threadIdx.x; i < HID * 9;   i += blockDim.x) { float w = W2[i]; sW2[i] = pk2(w, w); }
    if (threadIdx.x < 9) { float w = b2[threadIdx.x]; sB2[threadIdx.x] = pk2(w, w); }
    __syncthreads();

    const int famTid     = blk * (int)blockDim.x + (int)threadIdx.x;
    const int famThreads = nblk * (int)blockDim.x;
    constexpr int NP = EPT / 2;

    u64  dp[NP][DIN];     // MLP inputs packed across edge pair
    u64  atp[NP][3];      // attrs packed across edge pair
    u64  accp[NP][9];     // mobility accumulators packed across edge pair
    int  tgt[EPT];
    bool valid[EPT];

    #pragma unroll
    for (int p = 0; p < NP; p++) {
        float dv[2][DIN], av[2][3];
        #pragma unroll
        for (int s = 0; s < 2; s++) {
            int k = 2 * p + s;
            int e = famTid + k * famThreads;
            valid[k] = (e < E);
            int ee = valid[k] ? e : 0;
            int i;
            if (DIN == 3) {
                int j = edges[ee];
                i = edges[E + ee];
                dv[s][0] = x[3*j+0] - x[3*i+0];
                dv[s][1] = x[3*j+1] - x[3*i+1];
                dv[s][2] = x[3*j+2] - x[3*i+2];
            } else {
                int j  = edges[ee];
                int kk = edges[E + ee];
                i = edges[2*E + ee];
                float xk0 = x[3*kk+0], xk1 = x[3*kk+1], xk2 = x[3*kk+2];
                dv[s][0] = xk0 - x[3*j+0];
                dv[s][1] = xk1 - x[3*j+1];
                dv[s][2] = xk2 - x[3*j+2];
                dv[s][3] = x[3*i+0] - xk0;
                dv[s][4] = x[3*i+1] - xk1;
                dv[s][5] = x[3*i+2] - xk2;
            }
            tgt[k] = i;
            av[s][0] = attr[3*ee+0];
            av[s][1] = attr[3*ee+1];
            av[s][2] = attr[3*ee+2];
        }
        #pragma unroll
        for (int i = 0; i < DIN; i++) dp[p][i] = pk2(dv[0][i], dv[1][i]);
        #pragma unroll
        for (int i = 0; i < 3;   i++) atp[p][i] = pk2(av[0][i], av[1][i]);
        #pragma unroll
        for (int m = 0; m < 9;   m++) accp[p][m] = sB2[m];
    }

    // Mainloop: per hidden unit, one LDS.64 per weight, packed FMAs over pairs.
    #pragma unroll 2
    for (int h = 0; h < HID; h++) {
        u64 w1p[DIN];
        #pragma unroll
        for (int i = 0; i < DIN; i++) w1p[i] = sW1[i * HID + h];
        u64 bh = sB1[h];
        u64 w2p[9];
        #pragma unroll
        for (int m = 0; m < 9; m++) w2p[m] = sW2[h * 9 + m];

        #pragma unroll
        for (int p = 0; p < NP; p++) {
            u64 hv = bh;
            #pragma unroll
            for (int i = 0; i < DIN; i++) hv = ffma2(dp[p][i], w1p[i], hv);
            // packed ReLU: halves are just the register pair; FMNMX on alu pipe
            float lo, hi; upk2(hv, lo, hi);
            lo = fmaxf(lo, 0.0f); hi = fmaxf(hi, 0.0f);
            hv = pk2(lo, hi);
            #pragma unroll
            for (int m = 0; m < 9; m++) accp[p][m] = ffma2(hv, w2p[m], accp[p][m]);
        }
    }

    // Epilogue: packed matvec with attr, then scatter-add per edge.
    #pragma unroll
    for (int p = 0; p < NP; p++) {
        #pragma unroll
        for (int i = 0; i < 3; i++) {
            u64 t = fmul2(accp[p][3*i+2], atp[p][2]);
            t = ffma2(accp[p][3*i+1], atp[p][1], t);
            t = ffma2(accp[p][3*i+0], atp[p][0], t);
            float ylo, yhi; upk2(t, ylo, yhi);
            if (valid[2*p+0]) atomicAdd(&out[3*tgt[2*p+0] + i], ylo);
            if (valid[2*p+1]) atomicAdd(&out[3*tgt[2*p+1] + i], yhi);
        }
    }
}

__global__ __launch_bounds__(128, 4)
void fused_hignn_kernel(
    const float* __restrict__ x,
    const int* __restrict__ e2, const float* __restrict__ a2,
    const float* __restrict__ W1_2b, const float* __restrict__ b1_2b,
    const float* __restrict__ W2_2b, const float* __restrict__ b2_2b,
    const int* __restrict__ e3, const float* __restrict__ a3,
    const float* __restrict__ W1_3b, const float* __restrict__ b1_3b,
    const float* __restrict__ W2_3b, const float* __restrict__ b2_3b,
    const int* __restrict__ es, const float* __restrict__ as,
    const float* __restrict__ W1_s, const float* __restrict__ b1_s,
    const float* __restrict__ W2_s, const float* __restrict__ b2_s,
    float* __restrict__ out,
    int E2, int E3, int ES, int B2, int B3, int BS)
{
    __shared__ u64 smem[6 * HID + HID + 9 * HID + 9];
    int b = blockIdx.x;
    if (b < B2) {
        run_family<3, 4>(x, e2, a2, W1_2b, b1_2b, W2_2b, b2_2b, out, E2, b, B2, smem);
    } else if (b < B2 + B3) {
        run_family<6, 4>(x, e3, a3, W1_3b, b1_3b, W2_3b, b2_3b, out, E3, b - B2, B3, smem);
    } else {
        run_family<3, 4>(x, es, as, W1_s, b1_s, W2_s, b2_s, out, ES, b - B2 - B3, BS, smem);
    }
}

extern "C" void kernel_launch(void* const* d_in, const int* in_sizes, int n_in,
                              void* d_out, int out_size)
{
    const float* x   = (const float*)d_in[0];
    const int*   e2  = (const int*)  d_in[1];
    const int*   e3  = (const int*)  d_in[2];
    const int*   es  = (const int*)  d_in[3];
    const float* a2  = (const float*)d_in[5];
    const float* a3  = (const float*)d_in[6];
    const float* as  = (const float*)d_in[7];
    const float* W1_2b = (const float*)d_in[9];
    const float* b1_2b = (const float*)d_in[10];
    const float* W2_2b = (const float*)d_in[11];
    const float* b2_2b = (const float*)d_in[12];
    const float* W1_3b = (const float*)d_in[13];
    const float* b1_3b = (const float*)d_in[14];
    const float* W2_3b = (const float*)d_in[15];
    const float* b2_3b = (const float*)d_in[16];
    const float* W1_s  = (const float*)d_in[17];
    const float* b1_s  = (const float*)d_in[18];
    const float* W2_s  = (const float*)d_in[19];
    const float* b2_s  = (const float*)d_in[20];

    const int E2 = in_sizes[1] / 2;
    const int E3 = in_sizes[2] / 3;
    const int ES = in_sizes[3] / 2;

    float* out = (float*)d_out;

    zero_kernel<<<(out_size + 255) / 256, 256>>>(out, out_size);

    constexpr int EPT = 4;
    constexpr int BLK = 128;
    const int B2 = (E2 + EPT * BLK - 1) / (EPT * BLK);
    const int B3 = (E3 + EPT * BLK - 1) / (EPT * BLK);
    const int BS = (ES + EPT * BLK - 1) / (EPT * BLK);

    fused_hignn_kernel<<<B2 + B3 + BS, BLK>>>(
        x,
        e2, a2, W1_2b, b1_2b, W2_2b, b2_2b,
        e3, a3, W1_3b, b1_3b, W2_3b, b2_3b,
        es, as, W1_s, b1_s, W2_s, b2_s,
        out, E2, E3, ES, B2, B3, BS);
}